// round 17
// baseline (speedup 1.0000x reference)
#include <cuda_runtime.h>
#include <cstdint>
#include <cfloat>

#define BB 8
#define NN 8192
#define SS 1024
#define KK 32
#define CC 64
#define DD 128
#define EPSF 1e-5f

// output layout: new_xyz (8,1024,3), feature (8,128,1024), new_xyz, feature
#define OFF_F1  24576
#define OFF_NX2 1073152
#define OFF_F2  1097728

// mega-kernel block ranges (512 threads each)
#define FPS_B0   0
#define FEAT_B0  8             // 128 feat blocks
#define KNN_B0   136           // 512 knn blocks, 16 warp-queries each
#define L1L2_B0  648           // 1024 l1l2 blocks, 8 queries each (4 groups x 2)
#define TOT_BLKS 1672

// dynamic smem for l1l2: 4 groups x 25600 B
#define GRP_STRIDE 25600
#define DYN_SMEM   (4*GRP_STRIDE)

// ---------------- scratch (device globals; no allocation) ----------------
__device__ float g_f[BB*NN*CC];                 // 16 MB: per-point features
__device__ int   g_fps[BB*SS];
__device__ int   g_knn[BB*SS*KK];
__device__ int   g_prog[BB*32];                 // fps progress, 128B-padded per batch
__device__ int   g_kdone[512];                  // knn block completion flags
__device__ int   g_featdone[BB*32];             // feat blocks done per batch (padded)
// prepped (bn-folded) weights
__device__ float g_c1s[CC*3], g_t1[CC];
__device__ float g_c2s[CC*CC], g_t2c[CC];
__device__ float g_W1s[CC*DD];   // [d][o] = lconv1_w[o][d]      * s1l[o]
__device__ float g_Wd [CC*DD];   // [d][o] = (W[o][64+d]-W[o][d])* s1l[o]
__device__ float g_t1l[DD];
__device__ float g_W2s[DD*DD];   // [e][o] = lconv2_w[o][e] * s2l[o]
__device__ float g_t2l[DD];

// ---------------- helpers ----------------
__device__ __forceinline__ unsigned long long pk2(float a, float b) {
    unsigned long long r; asm("mov.b64 %0, {%1,%2};" : "=l"(r) : "f"(a), "f"(b)); return r;
}
__device__ __forceinline__ void upk2(unsigned long long v, float& a, float& b) {
    asm("mov.b64 {%0,%1}, %2;" : "=f"(a), "=f"(b) : "l"(v));
}
__device__ __forceinline__ unsigned long long add2(unsigned long long a, unsigned long long b) {
    unsigned long long r; asm("add.rn.f32x2 %0, %1, %2;" : "=l"(r) : "l"(a), "l"(b)); return r;
}
__device__ __forceinline__ unsigned long long mul2(unsigned long long a, unsigned long long b) {
    unsigned long long r; asm("mul.rn.f32x2 %0, %1, %2;" : "=l"(r) : "l"(a), "l"(b)); return r;
}
__device__ __forceinline__ void st_release(int* p, int v) {
    asm volatile("st.release.gpu.b32 [%0], %1;" :: "l"(p), "r"(v) : "memory");
}
__device__ __forceinline__ int ld_acquire(const int* p) {
    int v; asm volatile("ld.acquire.gpu.b32 %0, [%1];" : "=r"(v) : "l"(p) : "memory"); return v;
}
__device__ __forceinline__ void named_bar(int id) {
    asm volatile("bar.sync %0, %1;" :: "r"(id), "r"(128) : "memory");
}

// ---------------- prep: fold BN into weights + reset sync state ----------------
__global__ void prep_kernel(
    const float* __restrict__ c1w, const float* __restrict__ c2w,
    const float* __restrict__ l1w, const float* __restrict__ l2w,
    const float* __restrict__ b1g, const float* __restrict__ b1b, const float* __restrict__ b1m, const float* __restrict__ b1v,
    const float* __restrict__ b2g, const float* __restrict__ b2b, const float* __restrict__ b2m, const float* __restrict__ b2v,
    const float* __restrict__ g1g, const float* __restrict__ g1b, const float* __restrict__ g1m, const float* __restrict__ g1v,
    const float* __restrict__ g2g, const float* __restrict__ g2b, const float* __restrict__ g2m, const float* __restrict__ g2v)
{
    int t = blockIdx.x * blockDim.x + threadIdx.x;
    int st = gridDim.x * blockDim.x;
    if (t < BB*32) { g_prog[t] = 0; g_featdone[t] = 0; }
    if (t < 512) g_kdone[t] = 0;
    for (int i = t; i < CC*3; i += st) { int e = i/3; float s = b1g[e]*rsqrtf(b1v[e]+EPSF); g_c1s[i] = c1w[i]*s; }
    for (int e = t; e < CC; e += st)  { float s = b1g[e]*rsqrtf(b1v[e]+EPSF); g_t1[e] = b1b[e]-b1m[e]*s; }
    for (int i = t; i < CC*CC; i += st){ int f = i/CC; float s = b2g[f]*rsqrtf(b2v[f]+EPSF); g_c2s[i] = c2w[i]*s; }
    for (int f = t; f < CC; f += st)  { float s = b2g[f]*rsqrtf(b2v[f]+EPSF); g_t2c[f] = b2b[f]-b2m[f]*s; }
    for (int i = t; i < CC*DD; i += st){
        int d = i / DD, o = i % DD;
        float s = g1g[o]*rsqrtf(g1v[o]+EPSF);
        g_W1s[i] = l1w[o*DD + d]*s;
        g_Wd [i] = (l1w[o*DD + CC + d] - l1w[o*DD + d])*s;
    }
    for (int o = t; o < DD; o += st) { float s = g1g[o]*rsqrtf(g1v[o]+EPSF); g_t1l[o] = g1b[o]-g1m[o]*s; }
    for (int i = t; i < DD*DD; i += st){
        int e = i / DD, o = i % DD;
        float s = g2g[o]*rsqrtf(g2v[o]+EPSF);
        g_W2s[i] = l2w[o*DD + e]*s;
    }
    for (int o = t; o < DD; o += st) { float s = g2g[o]*rsqrtf(g2v[o]+EPSF); g_t2l[o] = g2b[o]-g2m[o]*s; }
}

// ---------------- MEGA: fps + feat + knn + l1l2, all pipelined ----------------
__global__ void __launch_bounds__(512) mega_kernel(const float* __restrict__ x, float* __restrict__ out)
{
    extern __shared__ char dyn[];
    int tid = threadIdx.x;
    int bid = blockIdx.x;

    if (bid < FEAT_B0) {
        // ---------------- FPS path (R16: 512-thr, f32x2, REDUX, coarse publish) ----------------
        __shared__ unsigned int pd[2][16];
        __shared__ unsigned int pi[2][16];
        int b = bid;
        int lane = tid & 31, wid = tid >> 5;
        const float* xb = x + (size_t)b * NN * 3;

        float rd[16];
        unsigned long long rx2[8], ry2[8], rz2[8];
#pragma unroll
        for (int jp = 0; jp < 8; jp++) {
            int i0 = tid + (2*jp)*512, i1 = i0 + 512;
            float ax = xb[i0*3], ay = xb[i0*3+1], az = xb[i0*3+2];
            float bx_ = xb[i1*3], by_ = xb[i1*3+1], bz_ = xb[i1*3+2];
            rx2[jp] = pk2(ax, bx_); ry2[jp] = pk2(ay, by_); rz2[jp] = pk2(az, bz_);
            rd[2*jp] = 1e10f; rd[2*jp+1] = 1e10f;
        }
        float cx = __ldg(xb), cy = __ldg(xb+1), cz = __ldg(xb+2);
        int far = 0;

        for (int t = 0; t < SS; t++) {
            if (tid == 0) {
                g_fps[b*SS + t] = far;
                int o1 = (b*SS + t) * 3;
                out[o1] = cx; out[o1+1] = cy; out[o1+2] = cz;
                out[OFF_NX2+o1] = cx; out[OFF_NX2+o1+1] = cy; out[OFF_NX2+o1+2] = cz;
                if ((t & 15) == 15) st_release(&g_prog[b*32], t + 1);   // coarse publish
            }
            unsigned long long nx = pk2(-cx, -cx), ny = pk2(-cy, -cy), nz = pk2(-cz, -cz);
#pragma unroll
            for (int jp = 0; jp < 8; jp++) {
                unsigned long long dx = add2(rx2[jp], nx);
                unsigned long long dy = add2(ry2[jp], ny);
                unsigned long long dz = add2(rz2[jp], nz);
                unsigned long long s  = add2(add2(mul2(dx,dx), mul2(dy,dy)), mul2(dz,dz));
                float s0, s1; upk2(s, s0, s1);
                rd[2*jp]   = fminf(rd[2*jp],   s0);
                rd[2*jp+1] = fminf(rd[2*jp+1], s1);
            }
            float m = rd[0];
#pragma unroll
            for (int j = 1; j < 16; j++) m = fmaxf(m, rd[j]);
            int j0 = 15;
#pragma unroll
            for (int j = 14; j >= 0; j--) if (rd[j] == m) j0 = j;
            unsigned int mb  = __float_as_uint(m);
            unsigned int inv = (unsigned)(NN-1 - (tid + j0*512));
            unsigned int wmax = __reduce_max_sync(0xffffffffu, mb);
            unsigned int winv = __reduce_max_sync(0xffffffffu, (mb == wmax) ? inv : 0u);
            if (lane == 0) { pd[t & 1][wid] = wmax; pi[t & 1][wid] = winv; }
            __syncthreads();
            unsigned int d2 = pd[t & 1][lane & 15];
            unsigned int i2 = pi[t & 1][lane & 15];
            unsigned int gmax = __reduce_max_sync(0xffffffffu, d2);
            unsigned int ginv = __reduce_max_sync(0xffffffffu, (d2 == gmax) ? i2 : 0u);
            far = NN-1 - (int)ginv;
            cx = __ldg(xb + far*3); cy = __ldg(xb + far*3 + 1); cz = __ldg(xb + far*3 + 2);
        }
    } else if (bid < KNN_B0) {
        // ---------------- feat path (+ done counter) ----------------
        __shared__ float sc1[CC*3], st1[CC], st2[CC];
        __shared__ float4 sc2[CC*16];
        for (int i = tid; i < CC*3; i += 512) sc1[i] = g_c1s[i];
        for (int i = tid; i < CC; i += 512) { st1[i] = g_t1[i]; st2[i] = g_t2c[i]; }
        for (int i = tid; i < CC*16; i += 512) sc2[i] = ((const float4*)g_c2s)[i];
        __syncthreads();

        int p = (bid - FEAT_B0) * 512 + tid;              // 0..65535
        float x0 = x[p*3], x1 = x[p*3+1], x2 = x[p*3+2];
        float h[CC];
#pragma unroll
        for (int e = 0; e < CC; e++)
            h[e] = fmaxf(fmaf(x2, sc1[e*3+2], fmaf(x1, sc1[e*3+1], x0*sc1[e*3])) + st1[e], 0.f);

        float* outf = g_f + (size_t)p * CC;
        for (int o = 0; o < CC; o++) {
            float a0=0.f, a1=0.f, a2=0.f, a3=0.f;
#pragma unroll
            for (int e4 = 0; e4 < 16; e4++) {
                float4 w = sc2[o*16 + e4];
                a0 = fmaf(h[e4*4+0], w.x, a0);
                a1 = fmaf(h[e4*4+1], w.y, a1);
                a2 = fmaf(h[e4*4+2], w.z, a2);
                a3 = fmaf(h[e4*4+3], w.w, a3);
            }
            outf[o] = fmaxf((a0+a1)+(a2+a3) + st2[o], 0.f);
        }
        __syncthreads();
        if (tid == 0) {
            __threadfence();
            int b = ((bid - FEAT_B0) * 512) >> 13;        // batch of this point range
            atomicAdd(&g_featdone[b*32], 1);
        }
    } else if (bid < L1L2_B0) {
        // ---------------- KNN path: 16 warp-queries; spin; publish completion flag ----------------
        __shared__ float px[512], py[512], pz[512];
        __shared__ int sready;
        int lane = tid & 31, wid = tid >> 5;
        int kblk = bid - KNN_B0;               // 0..511
        int qb = kblk * 16;                    // first query
        int b = qb >> 10;
        int need = (qb & 1023) + 16;
        if (tid == 0) {
            while (ld_acquire(&g_prog[b*32]) < need) __nanosleep(256);
            sready = 1;
        }
        __syncthreads();
        (void)sready;

        int sg = qb + wid;
        const float* xb = x + (size_t)b * NN * 3;
        int nq = g_fps[sg];
        float qx = xb[nq*3], qy = xb[nq*3+1], qz = xb[nq*3+2];

        unsigned long long cur = 0xFFFFFFFFFFFFFFFFull;
        unsigned long long worst = 0xFFFFFFFFFFFFFFFFull;

        for (int base = 0; base < NN; base += 512) {
            __syncthreads();
            {
                int n = base + tid;
                px[tid] = xb[n*3]; py[tid] = xb[n*3+1]; pz[tid] = xb[n*3+2];
            }
            __syncthreads();
#pragma unroll 4
            for (int s = 0; s < 512; s += 32) {
                int i = s + lane;
                float dx = qx - px[i], dy = qy - py[i], dz = qz - pz[i];
                float d = fmaf(dz, dz, fmaf(dy, dy, dx*dx));
                unsigned long long cand =
                    ((unsigned long long)__float_as_uint(d) << 32) | (unsigned)(base + i);
                unsigned int ball = __ballot_sync(0xffffffffu, cand < worst);
                while (ball) {
                    int src = __ffs(ball) - 1; ball &= ball - 1;
                    unsigned long long ck = __shfl_sync(0xffffffffu, cand, src);
                    if (ck < worst) {
                        unsigned int lt = __ballot_sync(0xffffffffu, cur < ck);
                        int pos = __popc(lt);
                        unsigned long long up = __shfl_up_sync(0xffffffffu, cur, 1);
                        if (lane > pos) cur = up;
                        if (lane == pos) cur = ck;
                        worst = __shfl_sync(0xffffffffu, cur, 31);
                    }
                }
            }
        }
        g_knn[(size_t)sg*KK + lane] = (int)(unsigned)(cur & 0xffffffffu);
        __syncthreads();
        if (tid == 0) st_release(&g_kdone[kblk], 1);
    } else {
        // ---------------- L1L2 path: 4 groups x 2 queries; spin; u inline; two-pass l2 ----------------
        __shared__ int go;
        int lb = bid - L1L2_B0;                // 0..1023
        int g = tid >> 7, t128 = tid & 127;
        char* gb = dyn + g * GRP_STRIDE;
        float4* gs = (float4*)gb;              // KK*16 float4 = 8192 B
        float*  hs = (float*)(gb + 8192);      // KK*DD floats = 16384 B
        float*  sc = (float*)(gb + 24576);     // 2*CC floats
        int*    kn = (int*)(gb + 25088);       // 2*KK ints
        int qbase = lb * 8;
        int b = qbase >> 10;

        if (tid == 0) {
            while (ld_acquire(&g_kdone[qbase >> 4]) == 0) __nanosleep(256);
            while (ld_acquire(&g_featdone[b*32]) < 16) __nanosleep(256);
            go = 1;
        }
        __syncthreads();
        (void)go;

        int sg0 = qbase + g*2;
        int s0 = sg0 & (SS-1);

        if (t128 < 2*KK) kn[t128] = g_knn[(size_t)sg0*KK + t128];
        {   // centroid features (2 x 64)
            int q = t128 >> 6, d = t128 & 63;
            sc[q*CC + d] = g_f[((size_t)(b*NN) + g_fps[sg0 + q])*CC + d];
        }
        named_bar(g + 1);

        // inline u: identical accumulator split/order as before; Wd shared across q
        float uu[2];
        {
            float a00=0.f,a01=0.f,a02=0.f,a03=0.f;
            float a10=0.f,a11=0.f,a12=0.f,a13=0.f;
#pragma unroll 4
            for (int d = 0; d < CC; d += 4) {
                float w0 = g_Wd[(d+0)*DD + t128];
                float w1_ = g_Wd[(d+1)*DD + t128];
                float w2_ = g_Wd[(d+2)*DD + t128];
                float w3 = g_Wd[(d+3)*DD + t128];
                a00 = fmaf(sc[0*CC+d+0], w0, a00);  a10 = fmaf(sc[1*CC+d+0], w0, a10);
                a01 = fmaf(sc[0*CC+d+1], w1_, a01); a11 = fmaf(sc[1*CC+d+1], w1_, a11);
                a02 = fmaf(sc[0*CC+d+2], w2_, a02); a12 = fmaf(sc[1*CC+d+2], w2_, a12);
                a03 = fmaf(sc[0*CC+d+3], w3, a03);  a13 = fmaf(sc[1*CC+d+3], w3, a13);
            }
            float t1l = g_t1l[t128];
            uu[0] = (a00+a01)+(a02+a03) + t1l;
            uu[1] = (a10+a11)+(a12+a13) + t1l;
        }

        float m[2];
#pragma unroll 1
        for (int q = 0; q < 2; q++) {
            // reload w1 each q (keeps register peak under the 128-reg cap)
            float w1[CC];
#pragma unroll
            for (int d = 0; d < CC; d++) w1[d] = g_W1s[d*DD + t128];
            named_bar(g + 1);            // prior q's hs/gs consumers done
#pragma unroll
            for (int j = 0; j < 4; j++) {
                int idx = t128 + j*128;
                int r = idx >> 4, c = idx & 15;
                int n = kn[q*KK + r];
                gs[idx] = ((const float4*)(g_f + ((size_t)(b*NN) + n)*CC))[c];
            }
            named_bar(g + 1);
            for (int k = 0; k < KK; k++) {
                float a0=0.f,a1=0.f,a2=0.f,a3=0.f;
#pragma unroll
                for (int d4 = 0; d4 < 16; d4++) {
                    float4 g4 = gs[k*16 + d4];
                    a0 = fmaf(g4.x, w1[d4*4+0], a0);
                    a1 = fmaf(g4.y, w1[d4*4+1], a1);
                    a2 = fmaf(g4.z, w1[d4*4+2], a2);
                    a3 = fmaf(g4.w, w1[d4*4+3], a3);
                }
                hs[k*DD + t128] = fmaxf((a0+a1)+(a2+a3) + uu[q], 0.f);
            }
            named_bar(g + 1);
            // l2 two-pass over e-halves; w2 column streamed through 64 registers
            float mm = -FLT_MAX;
#pragma unroll 1
            for (int kb = 0; kb < KK; kb += 8) {
                float acc[8];
                float w2h[64];
#pragma unroll
                for (int e = 0; e < 64; e++) w2h[e] = g_W2s[e*DD + t128];
#pragma unroll
                for (int j = 0; j < 8; j++) {
                    const float4* h4p = (const float4*)(hs + (kb + j)*DD);
                    float a0=0.f,a1=0.f,a2=0.f,a3=0.f;
#pragma unroll
                    for (int e4 = 0; e4 < 16; e4++) {
                        float4 h4 = h4p[e4];
                        a0 = fmaf(h4.x, w2h[e4*4+0], a0);
                        a1 = fmaf(h4.y, w2h[e4*4+1], a1);
                        a2 = fmaf(h4.z, w2h[e4*4+2], a2);
                        a3 = fmaf(h4.w, w2h[e4*4+3], a3);
                    }
                    acc[j] = (a0+a1)+(a2+a3);
                }
#pragma unroll
                for (int e = 0; e < 64; e++) w2h[e] = g_W2s[(64+e)*DD + t128];
#pragma unroll
                for (int j = 0; j < 8; j++) {
                    const float4* h4p = (const float4*)(hs + (kb + j)*DD + 64);
                    float b0=0.f,b1=0.f,b2=0.f,b3=0.f;
#pragma unroll
                    for (int e4 = 0; e4 < 16; e4++) {
                        float4 h4 = h4p[e4];
                        b0 = fmaf(h4.x, w2h[e4*4+0], b0);
                        b1 = fmaf(h4.y, w2h[e4*4+1], b1);
                        b2 = fmaf(h4.z, w2h[e4*4+2], b2);
                        b3 = fmaf(h4.w, w2h[e4*4+3], b3);
                    }
                    float tot = acc[j] + ((b0+b1)+(b2+b3));
                    mm = fmaxf(mm, tot);
                }
            }
            m[q] = fmaxf(mm + g_t2l[t128], 0.f);   // max-then-(+t2,relu): monotone
        }
        size_t off = (size_t)b*(DD*SS) + (size_t)t128*SS + s0;
        float2 v; v.x = m[0]; v.y = m[1];
        *(float2*)(out + OFF_F1 + off) = v;
        *(float2*)(out + OFF_F2 + off) = v;
    }
}

// ---------------- launch ----------------
extern "C" void kernel_launch(void* const* d_in, const int* in_sizes, int n_in,
                              void* d_out, int out_size)
{
    const float* x   = (const float*)d_in[0];
    const float* c1w = (const float*)d_in[1];
    const float* c2w = (const float*)d_in[2];
    const float* l1w = (const float*)d_in[3];
    const float* l2w = (const float*)d_in[4];
    const float* b1g = (const float*)d_in[5],  *b1b = (const float*)d_in[6],
               * b1m = (const float*)d_in[7],  *b1v = (const float*)d_in[8];
    const float* b2g = (const float*)d_in[9],  *b2b = (const float*)d_in[10],
               * b2m = (const float*)d_in[11], *b2v = (const float*)d_in[12];
    const float* g1g = (const float*)d_in[13], *g1b = (const float*)d_in[14],
               * g1m = (const float*)d_in[15], *g1v = (const float*)d_in[16];
    const float* g2g = (const float*)d_in[17], *g2b = (const float*)d_in[18],
               * g2m = (const float*)d_in[19], *g2v = (const float*)d_in[20];
    float* out = (float*)d_out;

    cudaFuncSetAttribute(mega_kernel, cudaFuncAttributeMaxDynamicSharedMemorySize, DYN_SMEM);

    prep_kernel<<<64, 256>>>(c1w, c2w, l1w, l2w,
                             b1g, b1b, b1m, b1v, b2g, b2b, b2m, b2v,
                             g1g, g1b, g1m, g1v, g2g, g2b, g2m, g2v);
    mega_kernel<<<TOT_BLKS, 512, DYN_SMEM>>>(x, out);
}